// round 10
// baseline (speedup 1.0000x reference)
#include <cuda_runtime.h>
#include <cuda_bf16.h>

// Problem constants: B=4, C=5, H=64, W=64, N=4096
#define BB 4
#define CC 5
#define WW 64
#define HW 4096
#define BSTRIDE 20480      // C*HW
#define NMAX 4096
#define M_TILE 6           // queries per attn block
#define NPAIR 3            // M_TILE / 2 packed query pairs
#define LOG2E 1.4426950408889634f
#define KVBLKS 64          // kv blocks in prep (256 threads each)
#define PARTS_PER_B 16     // KVBLKS / BB

typedef unsigned long long u64;

// -------- scratch (device globals; no allocation allowed) --------
__device__ float g_kf[BB * CC * HW];
__device__ float g_vf[BB * CC * HW];
__device__ float g_q[NMAX * CC];        // log2(e)-scaled query projections
__device__ int   g_perm[NMAX];
__device__ int   g_off[BB + 1];
__device__ int   g_blkoff[BB + 1];
__device__ float g_pmin[KVBLKS][CC];
__device__ float g_pmax[KVBLKS][CC];
__device__ float g_pnrm[KVBLKS];

__device__ __forceinline__ float ex2f(float x) {
    float r; asm("ex2.approx.f32 %0, %1;" : "=f"(r) : "f"(x)); return r;
}
__device__ __forceinline__ u64 pack2(float lo, float hi) {
    u64 r; asm("mov.b64 %0, {%1,%2};" : "=l"(r) : "f"(lo), "f"(hi)); return r;
}
__device__ __forceinline__ void unpack2(u64 v, float& lo, float& hi) {
    asm("mov.b64 {%0,%1}, %2;" : "=f"(lo), "=f"(hi) : "l"(v));
}
__device__ __forceinline__ u64 fma2(u64 a, u64 b, u64 c) {
    u64 d; asm("fma.rn.f32x2 %0, %1, %2, %3;" : "=l"(d) : "l"(a), "l"(b), "l"(c)); return d;
}
__device__ __forceinline__ u64 add2(u64 a, u64 b) {
    u64 d; asm("add.rn.f32x2 %0, %1, %2;" : "=l"(d) : "l"(a), "l"(b)); return d;
}

// ---------------------------------------------------------------
// Kernel 1 (fused), 256 threads/block:
//   blocks [0,64)            : k/v projection + y=x copy + per-block k stats
//   blocks [64,64+qblocks)   : q projection (log2-scaled)
//   last block               : counting sort by batch (MLP-batched loads)
// ---------------------------------------------------------------
__global__ void prep_kernel(const float* __restrict__ x,
                            const float* __restrict__ qw, const float* __restrict__ qb,
                            const float* __restrict__ kw, const float* __restrict__ kb,
                            const float* __restrict__ vw, const float* __restrict__ vb,
                            const int* __restrict__ ib, const int* __restrict__ ih,
                            const int* __restrict__ iw, int n,
                            float* __restrict__ y) {
    int tid = threadIdx.x;
    if (blockIdx.x < KVBLKS) {
        __shared__ float skw[25], skb[5], svw[25], svb[5];
        __shared__ float smin[8][CC], smax[8][CC], snrm[8];
        if (tid < 25) { skw[tid] = kw[tid]; svw[tid] = vw[tid]; }
        if (tid < 5)  { skb[tid] = kb[tid]; svb[tid] = vb[tid]; }
        __syncthreads();

        int t = blockIdx.x * 256 + tid;
        int b = t >> 12;
        int p = t & (HW - 1);
        const float* xb = x + b * BSTRIDE + p;
        float* yb = y + b * BSTRIDE + p;

        float xs[CC];
#pragma unroll
        for (int c = 0; c < CC; c++) { xs[c] = xb[c * HW]; yb[c * HW] = xs[c]; }

        float kk[CC]; float nrm = 0.0f;
#pragma unroll
        for (int o = 0; o < CC; o++) {
            float k = skb[o], v = svb[o];
#pragma unroll
            for (int c = 0; c < CC; c++) {
                k = fmaf(skw[o * CC + c], xs[c], k);
                v = fmaf(svw[o * CC + c], xs[c], v);
            }
            g_kf[b * BSTRIDE + o * HW + p] = k;
            g_vf[b * BSTRIDE + o * HW + p] = v;
            kk[o] = k;
            nrm = fmaf(k, k, nrm);
        }

        float mn[CC], mx[CC];
#pragma unroll
        for (int c = 0; c < CC; c++) { mn[c] = kk[c]; mx[c] = kk[c]; }
#pragma unroll
        for (int off = 16; off > 0; off >>= 1) {
#pragma unroll
            for (int c = 0; c < CC; c++) {
                mn[c] = fminf(mn[c], __shfl_xor_sync(0xffffffffu, mn[c], off));
                mx[c] = fmaxf(mx[c], __shfl_xor_sync(0xffffffffu, mx[c], off));
            }
            nrm = fmaxf(nrm, __shfl_xor_sync(0xffffffffu, nrm, off));
        }
        int wid = tid >> 5, lane = tid & 31;
        if (lane == 0) {
#pragma unroll
            for (int c = 0; c < CC; c++) { smin[wid][c] = mn[c]; smax[wid][c] = mx[c]; }
            snrm[wid] = nrm;
        }
        __syncthreads();
        if (tid < CC) {
            float a = smin[0][tid], bx = smax[0][tid];
#pragma unroll
            for (int w = 1; w < 8; w++) { a = fminf(a, smin[w][tid]); bx = fmaxf(bx, smax[w][tid]); }
            g_pmin[blockIdx.x][tid] = a;
            g_pmax[blockIdx.x][tid] = bx;
        }
        if (tid == CC) {
            float a = snrm[0];
#pragma unroll
            for (int w = 1; w < 8; w++) a = fmaxf(a, snrm[w]);
            g_pnrm[blockIdx.x] = a;
        }
    } else if (blockIdx.x < gridDim.x - 1) {
        __shared__ float sw[25], sb[5];
        if (tid < 25) sw[tid] = qw[tid];
        if (tid < 5)  sb[tid] = qb[tid];
        __syncthreads();
        int i = (blockIdx.x - KVBLKS) * 256 + tid;
        if (i >= n) return;
        int b = ib[i];
        int pix = ih[i] * WW + iw[i];
        const float* xb = x + b * BSTRIDE + pix;
        float xs[CC];
#pragma unroll
        for (int c = 0; c < CC; c++) xs[c] = xb[c * HW];
#pragma unroll
        for (int o = 0; o < CC; o++) {
            float q = sb[o];
#pragma unroll
            for (int c = 0; c < CC; c++) q = fmaf(sw[o * CC + c], xs[c], q);
            g_q[i * CC + o] = q * LOG2E;
        }
    } else {
        // counting sort by batch; loads MLP-batched up front.
        // Slot order is numerically irrelevant (per-query compute is
        // slot-independent), so atomic rank order is benign.
        __shared__ int scnt[BB], scur[BB];
        int myb[16];
#pragma unroll
        for (int j = 0; j < 16; j++) {
            int i = tid + j * 256;
            myb[j] = (i < n) ? ib[i] : -1;
        }
        if (tid < BB) scnt[tid] = 0;
        __syncthreads();
        int c0 = 0, c1 = 0, c2 = 0, c3 = 0;
#pragma unroll
        for (int j = 0; j < 16; j++) {
            c0 += (myb[j] == 0); c1 += (myb[j] == 1);
            c2 += (myb[j] == 2); c3 += (myb[j] == 3);
        }
        if (c0) atomicAdd(&scnt[0], c0);
        if (c1) atomicAdd(&scnt[1], c1);
        if (c2) atomicAdd(&scnt[2], c2);
        if (c3) atomicAdd(&scnt[3], c3);
        __syncthreads();
        if (tid == 0) {
            int acc = 0, bacc = 0;
            for (int b = 0; b < BB; b++) {
                int cnt = scnt[b];
                g_off[b] = acc; scur[b] = acc; acc += cnt;
                g_blkoff[b] = bacc; bacc += (cnt + M_TILE - 1) / M_TILE;
            }
            g_off[BB] = acc;
            g_blkoff[BB] = bacc;
        }
        __syncthreads();
#pragma unroll
        for (int j = 0; j < 16; j++) {
            int i = tid + j * 256;
            if (i < n) {
                int pos = atomicAdd(&scur[myb[j]], 1);
                g_perm[pos] = i;
            }
        }
    }
}

// ---------------------------------------------------------------
// Kernel 2: one-pass bounded-softmax attention, FFMA2-packed over the
// m-dimension: q2[pair][c] = (q_m0, q_m1), k/v broadcast-packed per
// position. Halves FMA-pipe cycles at ZERO extra q/oacc registers.
// Block-uniform true upper bound (min(separable,Cauchy) - 32 log2) ->
// no guard, no max alignment, plain sums.
// ---------------------------------------------------------------
#define POSWORK(K0, K1, K2, K3, K4, V0, V1, V2, V3, V4)               \
    do {                                                              \
        u64 kb0 = pack2(K0, K0), kb1 = pack2(K1, K1);                 \
        u64 kb2 = pack2(K2, K2), kb3 = pack2(K3, K3);                 \
        u64 kb4 = pack2(K4, K4);                                      \
        u64 vb0 = pack2(V0, V0), vb1 = pack2(V1, V1);                 \
        u64 vb2 = pack2(V2, V2), vb3 = pack2(V3, V3);                 \
        u64 vb4 = pack2(V4, V4);                                      \
        _Pragma("unroll")                                             \
        for (int pr = 0; pr < NPAIR; pr++) {                          \
            u64 e2 = fma2(q2[pr][0], kb0, nl2[pr]);                   \
            e2 = fma2(q2[pr][1], kb1, e2);                            \
            e2 = fma2(q2[pr][2], kb2, e2);                            \
            e2 = fma2(q2[pr][3], kb3, e2);                            \
            e2 = fma2(q2[pr][4], kb4, e2);                            \
            float e0, e1;                                             \
            unpack2(e2, e0, e1);                                      \
            u64 w2 = pack2(ex2f(e0), ex2f(e1));                       \
            ssum2[pr] = add2(ssum2[pr], w2);                          \
            oacc2[pr][0] = fma2(w2, vb0, oacc2[pr][0]);               \
            oacc2[pr][1] = fma2(w2, vb1, oacc2[pr][1]);               \
            oacc2[pr][2] = fma2(w2, vb2, oacc2[pr][2]);               \
            oacc2[pr][3] = fma2(w2, vb3, oacc2[pr][3]);               \
            oacc2[pr][4] = fma2(w2, vb4, oacc2[pr][4]);               \
        }                                                             \
    } while (0)

__global__ void __launch_bounds__(256, 2)
attn_kernel(const float* __restrict__ x,
            const int* __restrict__ ih, const int* __restrict__ iw,
            const float* __restrict__ gamma, float* __restrict__ y) {
    int tid = threadIdx.x;

    __shared__ int   s_boff[BB + 1], s_off[BB + 1];
    __shared__ int   s_n[M_TILE];
    __shared__ float s_kmn[CC], s_kmx[CC], s_knrm;
    __shared__ float s_red[M_TILE * 6 * 8];

    if (tid < BB + 1) { s_boff[tid] = g_blkoff[tid]; s_off[tid] = g_off[tid]; }
    __syncthreads();

    int blk = blockIdx.x;
    if (blk >= s_boff[BB]) return;
    int b = 0;
    while (blk >= s_boff[b + 1]) b++;
    int base = s_off[b] + (blk - s_boff[b]) * M_TILE;
    int end = s_off[b + 1];
    int mcnt = min(M_TILE, end - base);

    if (tid < M_TILE) s_n[tid] = (tid < mcnt) ? g_perm[base + tid] : -1;
    // finalize per-batch k stats from PARTS_PER_B partials (cheap, per block)
    if (tid >= 32 && tid < 32 + CC) {
        int c = tid - 32;
        float a = 3.0e38f;
#pragma unroll
        for (int k = 0; k < PARTS_PER_B; k++) a = fminf(a, g_pmin[b * PARTS_PER_B + k][c]);
        s_kmn[c] = a;
    } else if (tid >= 64 && tid < 64 + CC) {
        int c = tid - 64;
        float a = -3.0e38f;
#pragma unroll
        for (int k = 0; k < PARTS_PER_B; k++) a = fmaxf(a, g_pmax[b * PARTS_PER_B + k][c]);
        s_kmx[c] = a;
    } else if (tid == 96) {
        float a = 0.0f;
#pragma unroll
        for (int k = 0; k < PARTS_PER_B; k++) a = fmaxf(a, g_pnrm[b * PARTS_PER_B + k]);
        s_knrm = sqrtf(a);
    }
    __syncthreads();

    // load q and build packed pairs + packed bound seeds
    u64 q2[NPAIR][CC];
    u64 nl2[NPAIR];
    {
        float knrm = s_knrm;
        float qs[M_TILE][CC], nl[M_TILE];
#pragma unroll
        for (int m = 0; m < M_TILE; m++) {
            int nq = s_n[m];
            float sep = 0.0f, qq = 0.0f;
#pragma unroll
            for (int c = 0; c < CC; c++) {
                float v = (nq >= 0) ? __ldg(&g_q[nq * CC + c]) : 0.0f;
                qs[m][c] = v;
                sep += fmaxf(v * s_kmx[c], v * s_kmn[c]);
                qq = fmaf(v, v, qq);
            }
            nl[m] = 32.0f - fminf(sep, sqrtf(qq) * knrm);
        }
#pragma unroll
        for (int pr = 0; pr < NPAIR; pr++) {
#pragma unroll
            for (int c = 0; c < CC; c++)
                q2[pr][c] = pack2(qs[2 * pr][c], qs[2 * pr + 1][c]);
            nl2[pr] = pack2(nl[2 * pr], nl[2 * pr + 1]);
        }
    }

    const float2* kf2 = (const float2*)(g_kf + b * BSTRIDE);
    const float2* vf2 = (const float2*)(g_vf + b * BSTRIDE);

    u64 ssum2[NPAIR];
    u64 oacc2[NPAIR][CC];
#pragma unroll
    for (int pr = 0; pr < NPAIR; pr++) {
        ssum2[pr] = 0ull;
#pragma unroll
        for (int c = 0; c < CC; c++) oacc2[pr][c] = 0ull;
    }

#pragma unroll 1
    for (int it = 0; it < 8; it++) {
        int p2 = tid + it * 256;           // float2 index, 2048 per channel
        float2 k0 = kf2[p2];
        float2 k1 = kf2[2048 + p2];
        float2 k2 = kf2[2 * 2048 + p2];
        float2 k3 = kf2[3 * 2048 + p2];
        float2 k4 = kf2[4 * 2048 + p2];
        float2 v0 = vf2[p2];
        float2 v1 = vf2[2048 + p2];
        float2 v2 = vf2[2 * 2048 + p2];
        float2 v3 = vf2[3 * 2048 + p2];
        float2 v4 = vf2[4 * 2048 + p2];
        POSWORK(k0.x, k1.x, k2.x, k3.x, k4.x, v0.x, v1.x, v2.x, v3.x, v4.x);
        POSWORK(k0.y, k1.y, k2.y, k3.y, k4.y, v0.y, v1.y, v2.y, v3.y, v4.y);
    }

    // unpack to scalar per-m accumulators
    float ssum[M_TILE];
    float oacc[M_TILE][CC];
#pragma unroll
    for (int pr = 0; pr < NPAIR; pr++) {
        unpack2(ssum2[pr], ssum[2 * pr], ssum[2 * pr + 1]);
#pragma unroll
        for (int c = 0; c < CC; c++)
            unpack2(oacc2[pr][c], oacc[2 * pr][c], oacc[2 * pr + 1][c]);
    }

    int wid = tid >> 5, lane = tid & 31;

    // ---- sum reduction (bound uniform -> plain sums) ----
#pragma unroll
    for (int m = 0; m < M_TILE; m++) {
#pragma unroll
        for (int off = 16; off > 0; off >>= 1)
            ssum[m] += __shfl_xor_sync(0xffffffffu, ssum[m], off);
#pragma unroll
        for (int c = 0; c < CC; c++) {
#pragma unroll
            for (int off = 16; off > 0; off >>= 1)
                oacc[m][c] += __shfl_xor_sync(0xffffffffu, oacc[m][c], off);
        }
    }
    if (lane == 0) {
#pragma unroll
        for (int m = 0; m < M_TILE; m++) {
            s_red[(m * 6 + 0) * 8 + wid] = ssum[m];
#pragma unroll
            for (int c = 0; c < CC; c++)
                s_red[(m * 6 + 1 + c) * 8 + wid] = oacc[m][c];
        }
    }
    __syncthreads();

    if (tid < mcnt) {
        int m = tid;
        float s = 0.0f;
#pragma unroll
        for (int w = 0; w < 8; w++) s += s_red[(m * 6) * 8 + w];
        float inv = 1.0f / s;
        float g = gamma[0];
        int nq = s_n[m];
        int pix = ih[nq] * WW + iw[nq];
#pragma unroll
        for (int c = 0; c < CC; c++) {
            float oc = 0.0f;
#pragma unroll
            for (int w = 0; w < 8; w++) oc += s_red[(m * 6 + 1 + c) * 8 + w];
            int idx = b * BSTRIDE + c * HW + pix;
            y[idx] = fmaf(g, oc * inv, x[idx]);
        }
    }
}

// ---------------------------------------------------------------
// launch
// ---------------------------------------------------------------
extern "C" void kernel_launch(void* const* d_in, const int* in_sizes, int n_in,
                              void* d_out, int out_size) {
    const float* x     = (const float*)d_in[0];
    const float* qw    = (const float*)d_in[2];
    const float* qb    = (const float*)d_in[3];
    const float* kw    = (const float*)d_in[4];
    const float* kb    = (const float*)d_in[5];
    const float* vw    = (const float*)d_in[6];
    const float* vb    = (const float*)d_in[7];
    const float* gamma = (const float*)d_in[8];
    const int*   ib    = (const int*)d_in[9];
    const int*   ih    = (const int*)d_in[10];
    const int*   iw    = (const int*)d_in[11];
    float* y = (float*)d_out;

    int n = in_sizes[9];
    int qblocks = (n + 255) / 256;

    prep_kernel<<<KVBLKS + qblocks + 1, 256>>>(x, qw, qb, kw, kb, vw, vb, ib, ih, iw, n, y);

    int maxblk = (n + M_TILE - 1) / M_TILE + BB - 1;   // upper bound on working blocks
    attn_kernel<<<maxblk, 256>>>(x, ih, iw, gamma, y);
}

// round 11
// speedup vs baseline: 1.3125x; 1.3125x over previous
#include <cuda_runtime.h>
#include <cuda_bf16.h>

// Problem constants: B=4, C=5, H=64, W=64, N=4096
#define BB 4
#define CC 5
#define WW 64
#define HW 4096
#define BSTRIDE 20480      // C*HW
#define NMAX 4096
#define M_TILE 6           // queries per attn block
#define LOG2E 1.4426950408889634f
#define KVBLKS 64          // kv blocks in prep (256 threads each)
#define PARTS_PER_B 16     // KVBLKS / BB

// -------- scratch (device globals; no allocation allowed) --------
// interleaved k/v: per (batch, channel, pair) float4 = [k_even, k_odd, v_even, v_odd]
__device__ float4 g_kv[BB * CC * 2048];
__device__ float g_q[NMAX * CC];        // log2(e)-scaled query projections
__device__ int   g_perm[NMAX];
__device__ int   g_off[BB + 1];
__device__ int   g_blkoff[BB + 1];
__device__ float g_pmin[KVBLKS][CC];
__device__ float g_pmax[KVBLKS][CC];
__device__ float g_pnrm[KVBLKS];

__device__ __forceinline__ float ex2f(float x) {
    float r; asm("ex2.approx.f32 %0, %1;" : "=f"(r) : "f"(x)); return r;
}

// ---------------------------------------------------------------
// Kernel 1 (fused), 256 threads/block:
//   blocks [0,64)            : k/v projection (interleaved kv write) + y=x copy + k stats
//   blocks [64,64+qblocks)   : q projection (log2-scaled)
//   last block               : counting sort by batch (MLP-batched loads)
// ---------------------------------------------------------------
__global__ void prep_kernel(const float* __restrict__ x,
                            const float* __restrict__ qw, const float* __restrict__ qb,
                            const float* __restrict__ kw, const float* __restrict__ kb,
                            const float* __restrict__ vw, const float* __restrict__ vb,
                            const int* __restrict__ ib, const int* __restrict__ ih,
                            const int* __restrict__ iw, int n,
                            float* __restrict__ y) {
    int tid = threadIdx.x;
    if (blockIdx.x < KVBLKS) {
        __shared__ float skw[25], skb[5], svw[25], svb[5];
        __shared__ float smin[8][CC], smax[8][CC], snrm[8];
        if (tid < 25) { skw[tid] = kw[tid]; svw[tid] = vw[tid]; }
        if (tid < 5)  { skb[tid] = kb[tid]; svb[tid] = vb[tid]; }
        __syncthreads();

        int t = blockIdx.x * 256 + tid;
        int b = t >> 12;
        int p = t & (HW - 1);
        const float* xb = x + b * BSTRIDE + p;
        float* yb = y + b * BSTRIDE + p;

        float xs[CC];
#pragma unroll
        for (int c = 0; c < CC; c++) { xs[c] = xb[c * HW]; yb[c * HW] = xs[c]; }

        int p2 = p >> 1, half = p & 1;
        float kk[CC]; float nrm = 0.0f;
#pragma unroll
        for (int o = 0; o < CC; o++) {
            float k = skb[o], v = svb[o];
#pragma unroll
            for (int c = 0; c < CC; c++) {
                k = fmaf(skw[o * CC + c], xs[c], k);
                v = fmaf(svw[o * CC + c], xs[c], v);
            }
            float* dst = (float*)&g_kv[(b * CC + o) * 2048 + p2];
            dst[half] = k;
            dst[2 + half] = v;
            kk[o] = k;
            nrm = fmaf(k, k, nrm);
        }

        float mn[CC], mx[CC];
#pragma unroll
        for (int c = 0; c < CC; c++) { mn[c] = kk[c]; mx[c] = kk[c]; }
#pragma unroll
        for (int off = 16; off > 0; off >>= 1) {
#pragma unroll
            for (int c = 0; c < CC; c++) {
                mn[c] = fminf(mn[c], __shfl_xor_sync(0xffffffffu, mn[c], off));
                mx[c] = fmaxf(mx[c], __shfl_xor_sync(0xffffffffu, mx[c], off));
            }
            nrm = fmaxf(nrm, __shfl_xor_sync(0xffffffffu, nrm, off));
        }
        int wid = tid >> 5, lane = tid & 31;
        if (lane == 0) {
#pragma unroll
            for (int c = 0; c < CC; c++) { smin[wid][c] = mn[c]; smax[wid][c] = mx[c]; }
            snrm[wid] = nrm;
        }
        __syncthreads();
        if (tid < CC) {
            float a = smin[0][tid], bx = smax[0][tid];
#pragma unroll
            for (int w = 1; w < 8; w++) { a = fminf(a, smin[w][tid]); bx = fmaxf(bx, smax[w][tid]); }
            g_pmin[blockIdx.x][tid] = a;
            g_pmax[blockIdx.x][tid] = bx;
        }
        if (tid == CC) {
            float a = snrm[0];
#pragma unroll
            for (int w = 1; w < 8; w++) a = fmaxf(a, snrm[w]);
            g_pnrm[blockIdx.x] = a;
        }
    } else if (blockIdx.x < gridDim.x - 1) {
        __shared__ float sw[25], sb[5];
        if (tid < 25) sw[tid] = qw[tid];
        if (tid < 5)  sb[tid] = qb[tid];
        __syncthreads();
        int i = (blockIdx.x - KVBLKS) * 256 + tid;
        if (i >= n) return;
        int b = ib[i];
        int pix = ih[i] * WW + iw[i];
        const float* xb = x + b * BSTRIDE + pix;
        float xs[CC];
#pragma unroll
        for (int c = 0; c < CC; c++) xs[c] = xb[c * HW];
#pragma unroll
        for (int o = 0; o < CC; o++) {
            float q = sb[o];
#pragma unroll
            for (int c = 0; c < CC; c++) q = fmaf(sw[o * CC + c], xs[c], q);
            g_q[i * CC + o] = q * LOG2E;
        }
    } else {
        // counting sort by batch; loads MLP-batched up front.
        // Slot order is numerically irrelevant (per-query compute is
        // slot-independent), so atomic rank order is benign.
        __shared__ int scnt[BB], scur[BB];
        int myb[16];
#pragma unroll
        for (int j = 0; j < 16; j++) {
            int i = tid + j * 256;
            myb[j] = (i < n) ? ib[i] : -1;
        }
        if (tid < BB) scnt[tid] = 0;
        __syncthreads();
        int c0 = 0, c1 = 0, c2 = 0, c3 = 0;
#pragma unroll
        for (int j = 0; j < 16; j++) {
            c0 += (myb[j] == 0); c1 += (myb[j] == 1);
            c2 += (myb[j] == 2); c3 += (myb[j] == 3);
        }
        if (c0) atomicAdd(&scnt[0], c0);
        if (c1) atomicAdd(&scnt[1], c1);
        if (c2) atomicAdd(&scnt[2], c2);
        if (c3) atomicAdd(&scnt[3], c3);
        __syncthreads();
        if (tid == 0) {
            int acc = 0, bacc = 0;
            for (int b = 0; b < BB; b++) {
                int cnt = scnt[b];
                g_off[b] = acc; scur[b] = acc; acc += cnt;
                g_blkoff[b] = bacc; bacc += (cnt + M_TILE - 1) / M_TILE;
            }
            g_off[BB] = acc;
            g_blkoff[BB] = bacc;
        }
        __syncthreads();
#pragma unroll
        for (int j = 0; j < 16; j++) {
            int i = tid + j * 256;
            if (i < n) {
                int pos = atomicAdd(&scur[myb[j]], 1);
                g_perm[pos] = i;
            }
        }
    }
}

// ---------------------------------------------------------------
// Kernel 2: one-pass bounded-softmax attention. Same structure as the
// 29.2us best, but k/v arrive via 5 LDG.128 (interleaved float4) instead
// of 10 LDG.64 — half the LSU dispatch slots / L1 wavefront queue entries.
// Register double-buffered prefetch; M_TILE=6 per 256-thread block.
// Block-uniform true upper bound -> no guard, plain sums.
// ---------------------------------------------------------------
#define LOADKV(buf, idx)                                   \
    do {                                                   \
        int _p = (idx);                                    \
        buf[0] = kv[_p];                                   \
        buf[1] = kv[2048 + _p];                            \
        buf[2] = kv[2 * 2048 + _p];                        \
        buf[3] = kv[3 * 2048 + _p];                        \
        buf[4] = kv[4 * 2048 + _p];                        \
    } while (0)

#define COMPUTEKV(buf)                                                 \
    do {                                                               \
        _Pragma("unroll")                                              \
        for (int m = 0; m < M_TILE; m++) {                             \
            float ex = fmaf(q[m][0], buf[0].x, nlmax[m]);              \
            ex = fmaf(q[m][1], buf[1].x, ex);                          \
            ex = fmaf(q[m][2], buf[2].x, ex);                          \
            ex = fmaf(q[m][3], buf[3].x, ex);                          \
            ex = fmaf(q[m][4], buf[4].x, ex);                          \
            float ey = fmaf(q[m][0], buf[0].y, nlmax[m]);              \
            ey = fmaf(q[m][1], buf[1].y, ey);                          \
            ey = fmaf(q[m][2], buf[2].y, ey);                          \
            ey = fmaf(q[m][3], buf[3].y, ey);                          \
            ey = fmaf(q[m][4], buf[4].y, ey);                          \
            float wx = ex2f(ex);                                       \
            float wy = ex2f(ey);                                       \
            ssum[m] += wx + wy;                                        \
            oacc[m][0] = fmaf(wx, buf[0].z, fmaf(wy, buf[0].w, oacc[m][0])); \
            oacc[m][1] = fmaf(wx, buf[1].z, fmaf(wy, buf[1].w, oacc[m][1])); \
            oacc[m][2] = fmaf(wx, buf[2].z, fmaf(wy, buf[2].w, oacc[m][2])); \
            oacc[m][3] = fmaf(wx, buf[3].z, fmaf(wy, buf[3].w, oacc[m][3])); \
            oacc[m][4] = fmaf(wx, buf[4].z, fmaf(wy, buf[4].w, oacc[m][4])); \
        }                                                              \
    } while (0)

__global__ void __launch_bounds__(256, 2)
attn_kernel(const float* __restrict__ x,
            const int* __restrict__ ih, const int* __restrict__ iw,
            const float* __restrict__ gamma, float* __restrict__ y) {
    int tid = threadIdx.x;

    __shared__ int   s_boff[BB + 1], s_off[BB + 1];
    __shared__ int   s_n[M_TILE];
    __shared__ float s_kmn[CC], s_kmx[CC], s_knrm;
    __shared__ float s_red[M_TILE * 6 * 8];

    if (tid < BB + 1) { s_boff[tid] = g_blkoff[tid]; s_off[tid] = g_off[tid]; }
    __syncthreads();

    int blk = blockIdx.x;
    if (blk >= s_boff[BB]) return;
    int b = 0;
    while (blk >= s_boff[b + 1]) b++;
    int base = s_off[b] + (blk - s_boff[b]) * M_TILE;
    int end = s_off[b + 1];
    int mcnt = min(M_TILE, end - base);

    if (tid < M_TILE) s_n[tid] = (tid < mcnt) ? g_perm[base + tid] : -1;
    // finalize per-batch k stats from PARTS_PER_B partials (cheap, per block)
    if (tid >= 32 && tid < 32 + CC) {
        int c = tid - 32;
        float a = 3.0e38f;
#pragma unroll
        for (int k = 0; k < PARTS_PER_B; k++) a = fminf(a, g_pmin[b * PARTS_PER_B + k][c]);
        s_kmn[c] = a;
    } else if (tid >= 64 && tid < 64 + CC) {
        int c = tid - 64;
        float a = -3.0e38f;
#pragma unroll
        for (int k = 0; k < PARTS_PER_B; k++) a = fmaxf(a, g_pmax[b * PARTS_PER_B + k][c]);
        s_kmx[c] = a;
    } else if (tid == 96) {
        float a = 0.0f;
#pragma unroll
        for (int k = 0; k < PARTS_PER_B; k++) a = fmaxf(a, g_pnrm[b * PARTS_PER_B + k]);
        s_knrm = sqrtf(a);
    }
    __syncthreads();

    float q[M_TILE][CC];
#pragma unroll
    for (int m = 0; m < M_TILE; m++) {
        int nq = s_n[m];
#pragma unroll
        for (int c = 0; c < CC; c++)
            q[m][c] = (nq >= 0) ? __ldg(&g_q[nq * CC + c]) : 0.0f;
    }

    // nlmax[m] = 32 - min(separable, Cauchy) upper bound (block-uniform)
    float nlmax[M_TILE];
    {
        float knrm = s_knrm;
#pragma unroll
        for (int m = 0; m < M_TILE; m++) {
            float sep = 0.0f, qq = 0.0f;
#pragma unroll
            for (int c = 0; c < CC; c++) {
                sep += fmaxf(q[m][c] * s_kmx[c], q[m][c] * s_kmn[c]);
                qq = fmaf(q[m][c], q[m][c], qq);
            }
            float cau = sqrtf(qq) * knrm;
            nlmax[m] = 32.0f - fminf(sep, cau);
        }
    }

    const float4* kv = g_kv + b * CC * 2048;

    float ssum[M_TILE];
    float oacc[M_TILE][CC];
#pragma unroll
    for (int m = 0; m < M_TILE; m++) {
        ssum[m] = 0.0f;
#pragma unroll
        for (int c = 0; c < CC; c++) oacc[m][c] = 0.0f;
    }

    // register double-buffered sweep over 2048 pairs (8 iters of 256)
    float4 bufA[5], bufB[5];
    LOADKV(bufA, tid);
#pragma unroll 1
    for (int it = 0; it < 8; it += 2) {
        LOADKV(bufB, tid + (it + 1) * 256);
        COMPUTEKV(bufA);
        if (it + 2 < 8) LOADKV(bufA, tid + (it + 2) * 256);
        COMPUTEKV(bufB);
    }

    int wid = tid >> 5, lane = tid & 31;

    // ---- sum reduction (bound uniform -> plain sums) ----
#pragma unroll
    for (int m = 0; m < M_TILE; m++) {
#pragma unroll
        for (int off = 16; off > 0; off >>= 1)
            ssum[m] += __shfl_xor_sync(0xffffffffu, ssum[m], off);
#pragma unroll
        for (int c = 0; c < CC; c++) {
#pragma unroll
            for (int off = 16; off > 0; off >>= 1)
                oacc[m][c] += __shfl_xor_sync(0xffffffffu, oacc[m][c], off);
        }
    }
    if (lane == 0) {
#pragma unroll
        for (int m = 0; m < M_TILE; m++) {
            s_red[(m * 6 + 0) * 8 + wid] = ssum[m];
#pragma unroll
            for (int c = 0; c < CC; c++)
                s_red[(m * 6 + 1 + c) * 8 + wid] = oacc[m][c];
        }
    }
    __syncthreads();

    if (tid < mcnt) {
        int m = tid;
        float s = 0.0f;
#pragma unroll
        for (int w = 0; w < 8; w++) s += s_red[(m * 6) * 8 + w];
        float inv = 1.0f / s;
        float g = gamma[0];
        int nq = s_n[m];
        int pix = ih[nq] * WW + iw[nq];
#pragma unroll
        for (int c = 0; c < CC; c++) {
            float oc = 0.0f;
#pragma unroll
            for (int w = 0; w < 8; w++) oc += s_red[(m * 6 + 1 + c) * 8 + w];
            int idx = b * BSTRIDE + c * HW + pix;
            y[idx] = fmaf(g, oc * inv, x[idx]);
        }
    }
}

// ---------------------------------------------------------------
// launch
// ---------------------------------------------------------------
extern "C" void kernel_launch(void* const* d_in, const int* in_sizes, int n_in,
                              void* d_out, int out_size) {
    const float* x     = (const float*)d_in[0];
    const float* qw    = (const float*)d_in[2];
    const float* qb    = (const float*)d_in[3];
    const float* kw    = (const float*)d_in[4];
    const float* kb    = (const float*)d_in[5];
    const float* vw    = (const float*)d_in[6];
    const float* vb    = (const float*)d_in[7];
    const float* gamma = (const float*)d_in[8];
    const int*   ib    = (const int*)d_in[9];
    const int*   ih    = (const int*)d_in[10];
    const int*   iw    = (const int*)d_in[11];
    float* y = (float*)d_out;

    int n = in_sizes[9];
    int qblocks = (n + 255) / 256;

    prep_kernel<<<KVBLKS + qblocks + 1, 256>>>(x, qw, qb, kw, kb, vw, vb, ib, ih, iw, n, y);

    int maxblk = (n + M_TILE - 1) / M_TILE + BB - 1;   // upper bound on working blocks
    attn_kernel<<<maxblk, 256>>>(x, ih, iw, gamma, y);
}

// round 12
// speedup vs baseline: 1.3344x; 1.0167x over previous
#include <cuda_runtime.h>
#include <cuda_bf16.h>

// Problem constants: B=4, C=5, H=64, W=64, N=4096
#define BB 4
#define CC 5
#define WW 64
#define HW 4096
#define BSTRIDE 20480      // C*HW
#define NMAX 4096
#define M_TILE 7           // queries per attn block -> ~588 blocks = 2 waves @ 2 CTA/SM
#define LOG2E 1.4426950408889634f
#define KVBLKS 64          // kv blocks in prep (256 threads each)
#define PARTS_PER_B 16     // KVBLKS / BB

// -------- scratch (device globals; no allocation allowed) --------
// interleaved k/v: per (batch, channel, pair) float4 = [k_even, k_odd, v_even, v_odd]
__device__ float4 g_kv[BB * CC * 2048];
__device__ float g_q[NMAX * CC];        // log2(e)-scaled query projections
__device__ int   g_perm[NMAX];
__device__ int   g_off[BB + 1];
__device__ int   g_blkoff[BB + 1];
__device__ float g_pmin[KVBLKS][CC];
__device__ float g_pmax[KVBLKS][CC];
__device__ float g_pnrm[KVBLKS];

__device__ __forceinline__ float ex2f(float x) {
    float r; asm("ex2.approx.f32 %0, %1;" : "=f"(r) : "f"(x)); return r;
}

// ---------------------------------------------------------------
// Kernel 1 (fused), 256 threads/block:
//   blocks [0,64)            : k/v projection (interleaved kv write) + y=x copy + k stats
//   blocks [64,64+qblocks)   : q projection (log2-scaled)
//   last block               : counting sort by batch (MLP-batched loads)
// ---------------------------------------------------------------
__global__ void prep_kernel(const float* __restrict__ x,
                            const float* __restrict__ qw, const float* __restrict__ qb,
                            const float* __restrict__ kw, const float* __restrict__ kb,
                            const float* __restrict__ vw, const float* __restrict__ vb,
                            const int* __restrict__ ib, const int* __restrict__ ih,
                            const int* __restrict__ iw, int n,
                            float* __restrict__ y) {
    int tid = threadIdx.x;
    if (blockIdx.x < KVBLKS) {
        __shared__ float skw[25], skb[5], svw[25], svb[5];
        __shared__ float smin[8][CC], smax[8][CC], snrm[8];
        if (tid < 25) { skw[tid] = kw[tid]; svw[tid] = vw[tid]; }
        if (tid < 5)  { skb[tid] = kb[tid]; svb[tid] = vb[tid]; }
        __syncthreads();

        int t = blockIdx.x * 256 + tid;
        int b = t >> 12;
        int p = t & (HW - 1);
        const float* xb = x + b * BSTRIDE + p;
        float* yb = y + b * BSTRIDE + p;

        float xs[CC];
#pragma unroll
        for (int c = 0; c < CC; c++) { xs[c] = xb[c * HW]; yb[c * HW] = xs[c]; }

        int p2 = p >> 1, half = p & 1;
        float kk[CC]; float nrm = 0.0f;
#pragma unroll
        for (int o = 0; o < CC; o++) {
            float k = skb[o], v = svb[o];
#pragma unroll
            for (int c = 0; c < CC; c++) {
                k = fmaf(skw[o * CC + c], xs[c], k);
                v = fmaf(svw[o * CC + c], xs[c], v);
            }
            float* dst = (float*)&g_kv[(b * CC + o) * 2048 + p2];
            dst[half] = k;
            dst[2 + half] = v;
            kk[o] = k;
            nrm = fmaf(k, k, nrm);
        }

        float mn[CC], mx[CC];
#pragma unroll
        for (int c = 0; c < CC; c++) { mn[c] = kk[c]; mx[c] = kk[c]; }
#pragma unroll
        for (int off = 16; off > 0; off >>= 1) {
#pragma unroll
            for (int c = 0; c < CC; c++) {
                mn[c] = fminf(mn[c], __shfl_xor_sync(0xffffffffu, mn[c], off));
                mx[c] = fmaxf(mx[c], __shfl_xor_sync(0xffffffffu, mx[c], off));
            }
            nrm = fmaxf(nrm, __shfl_xor_sync(0xffffffffu, nrm, off));
        }
        int wid = tid >> 5, lane = tid & 31;
        if (lane == 0) {
#pragma unroll
            for (int c = 0; c < CC; c++) { smin[wid][c] = mn[c]; smax[wid][c] = mx[c]; }
            snrm[wid] = nrm;
        }
        __syncthreads();
        if (tid < CC) {
            float a = smin[0][tid], bx = smax[0][tid];
#pragma unroll
            for (int w = 1; w < 8; w++) { a = fminf(a, smin[w][tid]); bx = fmaxf(bx, smax[w][tid]); }
            g_pmin[blockIdx.x][tid] = a;
            g_pmax[blockIdx.x][tid] = bx;
        }
        if (tid == CC) {
            float a = snrm[0];
#pragma unroll
            for (int w = 1; w < 8; w++) a = fmaxf(a, snrm[w]);
            g_pnrm[blockIdx.x] = a;
        }
    } else if (blockIdx.x < gridDim.x - 1) {
        __shared__ float sw[25], sb[5];
        if (tid < 25) sw[tid] = qw[tid];
        if (tid < 5)  sb[tid] = qb[tid];
        __syncthreads();
        int i = (blockIdx.x - KVBLKS) * 256 + tid;
        if (i >= n) return;
        int b = ib[i];
        int pix = ih[i] * WW + iw[i];
        const float* xb = x + b * BSTRIDE + pix;
        float xs[CC];
#pragma unroll
        for (int c = 0; c < CC; c++) xs[c] = xb[c * HW];
#pragma unroll
        for (int o = 0; o < CC; o++) {
            float q = sb[o];
#pragma unroll
            for (int c = 0; c < CC; c++) q = fmaf(sw[o * CC + c], xs[c], q);
            g_q[i * CC + o] = q * LOG2E;
        }
    } else {
        // counting sort by batch; loads MLP-batched up front.
        // Slot order is numerically irrelevant (per-query compute is
        // slot-independent), so atomic rank order is benign.
        __shared__ int scnt[BB], scur[BB];
        int myb[16];
#pragma unroll
        for (int j = 0; j < 16; j++) {
            int i = tid + j * 256;
            myb[j] = (i < n) ? ib[i] : -1;
        }
        if (tid < BB) scnt[tid] = 0;
        __syncthreads();
        int c0 = 0, c1 = 0, c2 = 0, c3 = 0;
#pragma unroll
        for (int j = 0; j < 16; j++) {
            c0 += (myb[j] == 0); c1 += (myb[j] == 1);
            c2 += (myb[j] == 2); c3 += (myb[j] == 3);
        }
        if (c0) atomicAdd(&scnt[0], c0);
        if (c1) atomicAdd(&scnt[1], c1);
        if (c2) atomicAdd(&scnt[2], c2);
        if (c3) atomicAdd(&scnt[3], c3);
        __syncthreads();
        if (tid == 0) {
            int acc = 0, bacc = 0;
            for (int b = 0; b < BB; b++) {
                int cnt = scnt[b];
                g_off[b] = acc; scur[b] = acc; acc += cnt;
                g_blkoff[b] = bacc; bacc += (cnt + M_TILE - 1) / M_TILE;
            }
            g_off[BB] = acc;
            g_blkoff[BB] = bacc;
        }
        __syncthreads();
#pragma unroll
        for (int j = 0; j < 16; j++) {
            int i = tid + j * 256;
            if (i < n) {
                int pos = atomicAdd(&scur[myb[j]], 1);
                g_perm[pos] = i;
            }
        }
    }
}

// ---------------------------------------------------------------
// Kernel 2: one-pass bounded-softmax attention. M_TILE=7 per 256-thread
// block -> ~588 blocks = exactly 2 waves at 2 CTA/SM (was 2.32 waves ->
// quantized to 3 generations). Single-buffered 5x LDG.128 interleaved
// k/v loads (double-buffer measured neutral; regs freed for scheduling).
// Block-uniform true upper bound -> no guard, plain sums.
// ---------------------------------------------------------------
__global__ void __launch_bounds__(256, 2)
attn_kernel(const float* __restrict__ x,
            const int* __restrict__ ih, const int* __restrict__ iw,
            const float* __restrict__ gamma, float* __restrict__ y) {
    int tid = threadIdx.x;

    __shared__ int   s_boff[BB + 1], s_off[BB + 1];
    __shared__ int   s_n[M_TILE];
    __shared__ float s_kmn[CC], s_kmx[CC], s_knrm;
    __shared__ float s_red[M_TILE * 6 * 8];

    if (tid < BB + 1) { s_boff[tid] = g_blkoff[tid]; s_off[tid] = g_off[tid]; }
    __syncthreads();

    int blk = blockIdx.x;
    if (blk >= s_boff[BB]) return;
    int b = 0;
    while (blk >= s_boff[b + 1]) b++;
    int base = s_off[b] + (blk - s_boff[b]) * M_TILE;
    int end = s_off[b + 1];
    int mcnt = min(M_TILE, end - base);

    if (tid < M_TILE) s_n[tid] = (tid < mcnt) ? g_perm[base + tid] : -1;
    // finalize per-batch k stats from PARTS_PER_B partials (cheap, per block)
    if (tid >= 32 && tid < 32 + CC) {
        int c = tid - 32;
        float a = 3.0e38f;
#pragma unroll
        for (int k = 0; k < PARTS_PER_B; k++) a = fminf(a, g_pmin[b * PARTS_PER_B + k][c]);
        s_kmn[c] = a;
    } else if (tid >= 64 && tid < 64 + CC) {
        int c = tid - 64;
        float a = -3.0e38f;
#pragma unroll
        for (int k = 0; k < PARTS_PER_B; k++) a = fmaxf(a, g_pmax[b * PARTS_PER_B + k][c]);
        s_kmx[c] = a;
    } else if (tid == 96) {
        float a = 0.0f;
#pragma unroll
        for (int k = 0; k < PARTS_PER_B; k++) a = fmaxf(a, g_pnrm[b * PARTS_PER_B + k]);
        s_knrm = sqrtf(a);
    }
    __syncthreads();

    float q[M_TILE][CC];
#pragma unroll
    for (int m = 0; m < M_TILE; m++) {
        int nq = s_n[m];
#pragma unroll
        for (int c = 0; c < CC; c++)
            q[m][c] = (nq >= 0) ? __ldg(&g_q[nq * CC + c]) : 0.0f;
    }

    // nlmax[m] = 32 - min(separable, Cauchy) upper bound (block-uniform)
    float nlmax[M_TILE];
    {
        float knrm = s_knrm;
#pragma unroll
        for (int m = 0; m < M_TILE; m++) {
            float sep = 0.0f, qq = 0.0f;
#pragma unroll
            for (int c = 0; c < CC; c++) {
                sep += fmaxf(q[m][c] * s_kmx[c], q[m][c] * s_kmn[c]);
                qq = fmaf(q[m][c], q[m][c], qq);
            }
            float cau = sqrtf(qq) * knrm;
            nlmax[m] = 32.0f - fminf(sep, cau);
        }
    }

    const float4* kv = g_kv + b * CC * 2048;

    float ssum[M_TILE];
    float oacc[M_TILE][CC];
#pragma unroll
    for (int m = 0; m < M_TILE; m++) {
        ssum[m] = 0.0f;
#pragma unroll
        for (int c = 0; c < CC; c++) oacc[m][c] = 0.0f;
    }

    // sweep over 2048 pairs (8 iters of 256), unroll 2 for load/compute overlap
#pragma unroll 2
    for (int it = 0; it < 8; it++) {
        int p2 = tid + it * 256;
        float4 b0 = kv[p2];
        float4 b1 = kv[2048 + p2];
        float4 b2 = kv[2 * 2048 + p2];
        float4 b3 = kv[3 * 2048 + p2];
        float4 b4 = kv[4 * 2048 + p2];
#pragma unroll
        for (int m = 0; m < M_TILE; m++) {
            float ex = fmaf(q[m][0], b0.x, nlmax[m]);
            ex = fmaf(q[m][1], b1.x, ex);
            ex = fmaf(q[m][2], b2.x, ex);
            ex = fmaf(q[m][3], b3.x, ex);
            ex = fmaf(q[m][4], b4.x, ex);
            float ey = fmaf(q[m][0], b0.y, nlmax[m]);
            ey = fmaf(q[m][1], b1.y, ey);
            ey = fmaf(q[m][2], b2.y, ey);
            ey = fmaf(q[m][3], b3.y, ey);
            ey = fmaf(q[m][4], b4.y, ey);
            float wx = ex2f(ex);
            float wy = ex2f(ey);
            ssum[m] += wx + wy;
            oacc[m][0] = fmaf(wx, b0.z, fmaf(wy, b0.w, oacc[m][0]));
            oacc[m][1] = fmaf(wx, b1.z, fmaf(wy, b1.w, oacc[m][1]));
            oacc[m][2] = fmaf(wx, b2.z, fmaf(wy, b2.w, oacc[m][2]));
            oacc[m][3] = fmaf(wx, b3.z, fmaf(wy, b3.w, oacc[m][3]));
            oacc[m][4] = fmaf(wx, b4.z, fmaf(wy, b4.w, oacc[m][4]));
        }
    }

    int wid = tid >> 5, lane = tid & 31;

    // ---- sum reduction (bound uniform -> plain sums) ----
#pragma unroll
    for (int m = 0; m < M_TILE; m++) {
#pragma unroll
        for (int off = 16; off > 0; off >>= 1)
            ssum[m] += __shfl_xor_sync(0xffffffffu, ssum[m], off);
#pragma unroll
        for (int c = 0; c < CC; c++) {
#pragma unroll
            for (int off = 16; off > 0; off >>= 1)
                oacc[m][c] += __shfl_xor_sync(0xffffffffu, oacc[m][c], off);
        }
    }
    if (lane == 0) {
#pragma unroll
        for (int m = 0; m < M_TILE; m++) {
            s_red[(m * 6 + 0) * 8 + wid] = ssum[m];
#pragma unroll
            for (int c = 0; c < CC; c++)
                s_red[(m * 6 + 1 + c) * 8 + wid] = oacc[m][c];
        }
    }
    __syncthreads();

    if (tid < mcnt) {
        int m = tid;
        float s = 0.0f;
#pragma unroll
        for (int w = 0; w < 8; w++) s += s_red[(m * 6) * 8 + w];
        float inv = 1.0f / s;
        float g = gamma[0];
        int nq = s_n[m];
        int pix = ih[nq] * WW + iw[nq];
#pragma unroll
        for (int c = 0; c < CC; c++) {
            float oc = 0.0f;
#pragma unroll
            for (int w = 0; w < 8; w++) oc += s_red[(m * 6 + 1 + c) * 8 + w];
            int idx = b * BSTRIDE + c * HW + pix;
            y[idx] = fmaf(g, oc * inv, x[idx]);
        }
    }
}

// ---------------------------------------------------------------
// launch
// ---------------------------------------------------------------
extern "C" void kernel_launch(void* const* d_in, const int* in_sizes, int n_in,
                              void* d_out, int out_size) {
    const float* x     = (const float*)d_in[0];
    const float* qw    = (const float*)d_in[2];
    const float* qb    = (const float*)d_in[3];
    const float* kw    = (const float*)d_in[4];
    const float* kb    = (const float*)d_in[5];
    const float* vw    = (const float*)d_in[6];
    const float* vb    = (const float*)d_in[7];
    const float* gamma = (const float*)d_in[8];
    const int*   ib    = (const int*)d_in[9];
    const int*   ih    = (const int*)d_in[10];
    const int*   iw    = (const int*)d_in[11];
    float* y = (float*)d_out;

    int n = in_sizes[9];
    int qblocks = (n + 255) / 256;

    prep_kernel<<<KVBLKS + qblocks + 1, 256>>>(x, qw, qb, kw, kb, vw, vb, ib, ih, iw, n, y);

    int maxblk = (n + M_TILE - 1) / M_TILE + BB - 1;   // upper bound on working blocks
    attn_kernel<<<maxblk, 256>>>(x, ih, iw, gamma, y);
}